// round 16
// baseline (speedup 1.0000x reference)
#include <cuda_runtime.h>
#include <cuda_fp16.h>
#include <cstdint>

// ============================================================================
// VQ forward v16: fp16-accumulate mma.sync approx GEMM (fp16 inputs, margin
// widened for fp16 acc noise) -> candidate filter -> exact fp32 rescore.
// Exact-bits contract (validated R7/R10/R11/R15): d = fl(fl(a_n+b_k) - 2C),
// C = ascending-k single-accumulator fp32 FFMA chain, ties -> lowest index.
// ============================================================================

namespace vq16 {

constexpr int DIM  = 512;
constexpr int KCNT = 8192;
constexpr int NTOK = 32768;
constexpr int BM   = 128;
constexpr int BN   = 128;
constexpr int CAP  = 256;
// margin: fp16 input worst-case (~3.3e-3) + ~10 sigma of fp16-acc pair noise
constexpr float MARGIN = 0.08f;

constexpr int LDA = 520;           // f16 (512+8): ldmatrix A rows r%8 distinct
constexpr int LDB = 40;            // f16 (32+8):  B rows 5n%8 distinct
constexpr int LDC = 136;           // f16 (128+8): scan rows (r+q)%8 spread
constexpr int BK  = 32;
constexpr int NBUF = 4;
constexpr int BUFSZ = BN * LDB * 2;               // 10240 B
constexpr int SM_AS = 0;                          // 128*520*2 = 133120
constexpr int SM_BS = SM_AS + BM * LDA * 2;       // 4*10240   =  40960
constexpr int SM_CS = SM_BS + NBUF * BUFSZ;       // 128*136*2 =  34816
constexpr int SM_TOT = SM_CS + BM * LDC * 2;      // 208896 B

__device__ float g_nrm[KCNT + NTOK];   // [0,KCNT): ||e||^2 ; rest: ||z||^2
__device__ int   g_sel[NTOK];
__device__ float g_prt[NTOK];
__device__ __half g_embh[KCNT * DIM];
__device__ int   g_cnt[NTOK];
__device__ int   g_cand[(size_t)NTOK * CAP];
__device__ float g_cval[(size_t)NTOK * CAP];

// ----------------- PTX helpers (baseline ISA) -------------------------------
__device__ __forceinline__ void cp_async16(uint32_t dst, const void* src) {
    asm volatile("cp.async.ca.shared.global [%0], [%1], 16;" :: "r"(dst), "l"(src));
}
__device__ __forceinline__ void cp_commit() {
    asm volatile("cp.async.commit_group;" ::: "memory");
}
template <int N>
__device__ __forceinline__ void cp_wait() {
    asm volatile("cp.async.wait_group %0;" :: "n"(N) : "memory");
}
__device__ __forceinline__ void ldsm4(uint32_t* r, uint32_t a) {
    asm volatile("ldmatrix.sync.aligned.m8n8.x4.shared.b16 {%0,%1,%2,%3}, [%4];"
                 : "=r"(r[0]), "=r"(r[1]), "=r"(r[2]), "=r"(r[3]) : "r"(a));
}
// fp16-accumulate mma: D/C are 2 b32 regs (4 halves): reg0=row g, reg1=row g+8.
__device__ __forceinline__ void mma16816h(uint32_t* c, const uint32_t* a,
                                          uint32_t b0, uint32_t b1) {
    asm volatile(
        "mma.sync.aligned.m16n8k16.row.col.f16.f16.f16.f16 "
        "{%0,%1}, {%2,%3,%4,%5}, {%6,%7}, {%0,%1};"
        : "+r"(c[0]), "+r"(c[1])
        : "r"(a[0]), "r"(a[1]), "r"(a[2]), "r"(a[3]), "r"(b0), "r"(b1));
}

// ---------------------------------------------------------------------------
// Exact fp32 row norms (validated; order argmin-irrelevant).
// ---------------------------------------------------------------------------
__global__ void norms_fused(const float* __restrict__ emb,
                            const float* __restrict__ z) {
    const int gw = (blockIdx.x * 256 + threadIdx.x) >> 5;
    const int lane = threadIdx.x & 31;
    const float* src = (gw < KCNT) ? (emb + (size_t)gw * DIM)
                                   : (z + (size_t)(gw - KCNT) * DIM);
    float acc = 0.f;
    #pragma unroll
    for (int j = 0; j < DIM / 32; j++) {
        float v = src[lane + (j << 5)];
        acc = __fadd_rn(acc, __fmul_rn(v, v));
    }
    #pragma unroll
    for (int sh = 16; sh; sh >>= 1)
        acc = __fadd_rn(acc, __shfl_down_sync(0xffffffffu, acc, sh));
    if (lane == 0) g_nrm[gw] = acc;
}

// emb fp32 -> fp16 (rn).
__global__ void prep(const float* __restrict__ emb) {
    const int i = blockIdx.x * 256 + threadIdx.x;   // [0, 1048576)
    float4 v = reinterpret_cast<const float4*>(emb)[i];
    reinterpret_cast<__half2*>(g_embh)[2*i]   = __floats2half2_rn(v.x, v.y);
    reinterpret_cast<__half2*>(g_embh)[2*i+1] = __floats2half2_rn(v.z, v.w);
}

// ---------------------------------------------------------------------------
// Approx pass: mma.sync fp16 acc. CTA = 128 z rows resident (f16). 8 warps
// (4m x 2n), warp tile 32x64. K chunked by 32, 4-buffer cp.async pipeline,
// ONE barrier per chunk. Single-phase half epilogue (Cs 128x128 f16) ->
// per-row running max + margin push (single writer per row).
// ---------------------------------------------------------------------------
__global__ __launch_bounds__(256, 1)
void tc_pass(const float* __restrict__ z) {
    extern __shared__ char smraw[];
    __half* As = reinterpret_cast<__half*>(smraw + SM_AS);
    __half* Cs = reinterpret_cast<__half*>(smraw + SM_CS);
    const uint32_t smA = (uint32_t)__cvta_generic_to_shared(smraw + SM_AS);
    const uint32_t smB = (uint32_t)__cvta_generic_to_shared(smraw + SM_BS);

    const int tid  = threadIdx.x;
    const int wid  = tid >> 5;
    const int lane = tid & 31;
    const int wm   = wid & 3;          // 4 m-groups of 32 rows
    const int wn   = wid >> 2;         // 2 n-groups of 64 cols
    const int row0 = blockIdx.x * BM;

    // Stage A: z rows -> f16 row-major [128][LDA].
    for (int i = tid; i < BM * 256; i += 256) {
        const int r = i >> 8, c2 = i & 255;
        float2 f = *reinterpret_cast<const float2*>(z + (size_t)(row0 + r) * DIM + 2 * c2);
        *reinterpret_cast<__half2*>(As + r * LDA + 2 * c2) = __floats2half2_rn(f.x, f.y);
    }
    __syncthreads();

    // ldmatrix lane address bases (bytes).
    const uint32_t aBase = smA +
        (uint32_t)(((wm * 32 + (lane & 15)) * LDA + ((lane >> 4) << 3)) * 2);
    // B non-trans: row = n-group base + (lane&15); k-half = (lane>>4)*8.
    const uint32_t bLaneOff =
        (uint32_t)(((wn * 64 + (lane & 15)) * LDB + ((lane >> 4) << 3)) * 2);

    // cp.async staging: 2 x 16B per thread per chunk.
    const int csR0 = tid >> 1;
    const int csP0 = (tid & 1) << 1;
    float runmax = -3.4e38f;
    int   ccnt   = 0;

    for (int ct = 0; ct < KCNT / BN; ct++) {
        const int col0 = ct * BN;
        const __half* ebase = g_embh + (size_t)col0 * DIM;

        uint32_t acc[2][8][2];
        #pragma unroll
        for (int mi = 0; mi < 2; mi++)
            #pragma unroll
            for (int nj = 0; nj < 8; nj++) { acc[mi][nj][0] = 0u; acc[mi][nj][1] = 0u; }

        // prologue: chunks 0,1 -> buffers 0,1 (128 rows x 64B each)
        #pragma unroll
        for (int s = 0; s < 2; s++) {
            #pragma unroll
            for (int u = 0; u < 2; u++) {
                const int p = (csP0 + u) << 4;
                cp_async16(smB + s * BUFSZ + csR0 * (LDB * 2) + p,
                           reinterpret_cast<const char*>(ebase) +
                               (size_t)csR0 * DIM * 2 + s * BK * 2 + p);
            }
            cp_commit();
        }

        #pragma unroll 4
        for (int kc = 0; kc < DIM / BK; kc++) {          // 16 chunks
            if (kc + 2 < DIM / BK) {
                const int b = (kc + 2) & (NBUF - 1);
                #pragma unroll
                for (int u = 0; u < 2; u++) {
                    const int p = (csP0 + u) << 4;
                    cp_async16(smB + b * BUFSZ + csR0 * (LDB * 2) + p,
                               reinterpret_cast<const char*>(ebase) +
                                   (size_t)csR0 * DIM * 2 + (kc + 2) * BK * 2 + p);
                }
                cp_commit();
                cp_wait<2>();
            } else if (kc + 2 == DIM / BK) {
                cp_wait<1>();
            } else {
                cp_wait<0>();
            }
            __syncthreads();

            const uint32_t bufB = smB + (kc & (NBUF - 1)) * BUFSZ + bLaneOff;
            #pragma unroll
            for (int ks = 0; ks < 2; ks++) {
                uint32_t af[2][4];
                ldsm4(af[0], aBase + (kc * BK + ks * 16) * 2);
                ldsm4(af[1], aBase + (kc * BK + ks * 16) * 2 + 16 * LDA * 2);
                #pragma unroll
                for (int j = 0; j < 4; j++) {            // 4 x n16 blocks
                    uint32_t bf[4];
                    ldsm4(bf, bufB + (j * 16 * LDB + ks * 16) * 2);
                    #pragma unroll
                    for (int mi = 0; mi < 2; mi++) {
                        mma16816h(acc[mi][2*j],   af[mi], bf[0], bf[2]);
                        mma16816h(acc[mi][2*j+1], af[mi], bf[1], bf[3]);
                    }
                }
            }
        }
        __syncthreads();   // all reads of B bufs done before next-tile writes

        // Single-phase epilogue: all 8 warps store their half2 accs.
        #pragma unroll
        for (int mi = 0; mi < 2; mi++)
            #pragma unroll
            for (int nj = 0; nj < 8; nj++) {
                const int r = wm * 32 + mi * 16 + (lane >> 2);
                const int c = wn * 64 + nj * 8 + (lane & 3) * 2;
                *reinterpret_cast<uint32_t*>(Cs + r * LDC + c)       = acc[mi][nj][0];
                *reinterpret_cast<uint32_t*>(Cs + (r + 8) * LDC + c) = acc[mi][nj][1];
            }
        __syncthreads();

        // Per-row running max + margin candidate push (thread tid owns row tid).
        if (tid < BM) {
            const uint4* cr = reinterpret_cast<const uint4*>(Cs + tid * LDC);
            float mx = runmax;
            #pragma unroll
            for (int q = 0; q < 16; q++) {               // 16 x 8 halves
                const uint4 u = cr[q];
                const float2 f0 = __half22float2(*reinterpret_cast<const __half2*>(&u.x));
                const float2 f1 = __half22float2(*reinterpret_cast<const __half2*>(&u.y));
                const float2 f2 = __half22float2(*reinterpret_cast<const __half2*>(&u.z));
                const float2 f3 = __half22float2(*reinterpret_cast<const __half2*>(&u.w));
                mx = fmaxf(mx, fmaxf(fmaxf(fmaxf(f0.x, f0.y), fmaxf(f1.x, f1.y)),
                                     fmaxf(fmaxf(f2.x, f2.y), fmaxf(f3.x, f3.y))));
            }
            runmax = mx;
            const float thr = mx - MARGIN;
            const int rowG = row0 + tid;
            const size_t base = (size_t)rowG * CAP;
            #pragma unroll
            for (int q = 0; q < 16; q++) {
                const uint4 u = cr[q];
                const int kb = col0 + 8 * q;
                const float2 f0 = __half22float2(*reinterpret_cast<const __half2*>(&u.x));
                const float2 f1 = __half22float2(*reinterpret_cast<const __half2*>(&u.y));
                const float2 f2 = __half22float2(*reinterpret_cast<const __half2*>(&u.z));
                const float2 f3 = __half22float2(*reinterpret_cast<const __half2*>(&u.w));
                if (f0.x >= thr) { if (ccnt < CAP) { g_cand[base+ccnt]=kb;   g_cval[base+ccnt]=f0.x; } ccnt++; }
                if (f0.y >= thr) { if (ccnt < CAP) { g_cand[base+ccnt]=kb+1; g_cval[base+ccnt]=f0.y; } ccnt++; }
                if (f1.x >= thr) { if (ccnt < CAP) { g_cand[base+ccnt]=kb+2; g_cval[base+ccnt]=f1.x; } ccnt++; }
                if (f1.y >= thr) { if (ccnt < CAP) { g_cand[base+ccnt]=kb+3; g_cval[base+ccnt]=f1.y; } ccnt++; }
                if (f2.x >= thr) { if (ccnt < CAP) { g_cand[base+ccnt]=kb+4; g_cval[base+ccnt]=f2.x; } ccnt++; }
                if (f2.y >= thr) { if (ccnt < CAP) { g_cand[base+ccnt]=kb+5; g_cval[base+ccnt]=f2.y; } ccnt++; }
                if (f3.x >= thr) { if (ccnt < CAP) { g_cand[base+ccnt]=kb+6; g_cval[base+ccnt]=f3.x; } ccnt++; }
                if (f3.y >= thr) { if (ccnt < CAP) { g_cand[base+ccnt]=kb+7; g_cval[base+ccnt]=f3.y; } ccnt++; }
            }
        }
        __syncthreads();
    }
    if (tid < BM) g_cnt[row0 + tid] = ccnt;
}

// ---------------------------------------------------------------------------
// Exact rescore: warp per row, candidate per lane (validated R11/R15).
// Identical fp32 chain; prune vs global candidate max with the same margin.
// ---------------------------------------------------------------------------
__device__ __forceinline__ void exact_score(const float4* __restrict__ zr,
                                            const float* __restrict__ emb,
                                            float an, int k,
                                            float& bv, int& bi) {
    const float4* er = reinterpret_cast<const float4*>(emb + (size_t)k * DIM);
    float acc = 0.f;
    #pragma unroll 8
    for (int q = 0; q < DIM / 4; q++) {
        const float4 a = zr[q], b = er[q];
        acc = __fmaf_rn(a.x, b.x, acc);
        acc = __fmaf_rn(a.y, b.y, acc);
        acc = __fmaf_rn(a.z, b.z, acc);
        acc = __fmaf_rn(a.w, b.w, acc);
    }
    const float t = __fadd_rn(an, g_nrm[k]);
    const float v = __fmaf_rn(-2.f, acc, t);
    if (v < bv || (v == bv && k < bi)) { bv = v; bi = k; }
}

__global__ void rescore(const float* __restrict__ z, const float* __restrict__ emb) {
    const int n    = (blockIdx.x * 256 + threadIdx.x) >> 5;
    const int lane = threadIdx.x & 31;
    if (n >= NTOK) return;
    const float an = g_nrm[KCNT + n];
    const float4* zr = reinterpret_cast<const float4*>(z + (size_t)n * DIM);
    const int cnt = g_cnt[n];
    float bv = 3.4e38f;
    int   bi = 0x7fffffff;

    if (cnt > CAP) {
        for (int k = lane; k < KCNT; k += 32)
            exact_score(zr, emb, an, k, bv, bi);
    } else {
        const size_t base = (size_t)n * CAP;
        float cmax = -3.4e38f;
        for (int s = lane; s < cnt; s += 32) cmax = fmaxf(cmax, g_cval[base + s]);
        #pragma unroll
        for (int o = 16; o; o >>= 1)
            cmax = fmaxf(cmax, __shfl_xor_sync(0xffffffffu, cmax, o));
        const float thr = cmax - MARGIN;
        for (int s = lane; s < cnt; s += 32) {
            if (g_cval[base + s] < thr) continue;
            exact_score(zr, emb, an, g_cand[base + s], bv, bi);
        }
    }
    #pragma unroll
    for (int o = 16; o; o >>= 1) {
        const float v2 = __shfl_xor_sync(0xffffffffu, bv, o);
        const int   i2 = __shfl_xor_sync(0xffffffffu, bi, o);
        if (v2 < bv || (v2 == bv && i2 < bi)) { bv = v2; bi = i2; }
    }
    if (lane == 0) g_sel[n] = bi;
}

// ---------------------------------------------------------------------------
__global__ void finalize(const float* __restrict__ z, const float* __restrict__ emb,
                         float* __restrict__ out, int N) {
    const int half = threadIdx.x >> 7;
    const int lt   = threadIdx.x & 127;
    const int n    = blockIdx.x * 2 + half;
    const int k    = g_sel[n];
    const float* zr = z + (size_t)n * DIM;
    const float* er = emb + (size_t)k * DIM;
    float* o = out + 1 + (size_t)n * DIM;
    float s = 0.f;
    #pragma unroll
    for (int j = 0; j < DIM / 128; j++) {
        const int c = lt + j * 128;
        const float zv = zr[c];
        const float dx = __fadd_rn(er[c], -zv);
        o[c] = __fadd_rn(zv, dx);
        s = __fmaf_rn(dx, dx, s);
    }
    #pragma unroll
    for (int sh = 16; sh; sh >>= 1) s += __shfl_down_sync(0xffffffffu, s, sh);
    __shared__ float ws[8];
    if ((lt & 31) == 0) ws[half * 4 + (lt >> 5)] = s;
    __syncthreads();
    if (lt == 0) {
        g_prt[n] = ws[half*4] + ws[half*4+1] + ws[half*4+2] + ws[half*4+3];
        out[1 + (size_t)N * DIM + n] = (float)k;
    }
}

__global__ void reduce_loss(float* __restrict__ out, int N) {
    __shared__ float sm[512];
    float s = 0.f;
    for (int i = threadIdx.x; i < N; i += 512) s += g_prt[i];
    sm[threadIdx.x] = s;
    __syncthreads();
    for (int o = 256; o; o >>= 1) {
        if (threadIdx.x < o) sm[threadIdx.x] += sm[threadIdx.x + o];
        __syncthreads();
    }
    if (threadIdx.x == 0) out[0] = 2.f * sm[0] / ((float)N * (float)DIM);
}

}  // namespace vq16

// ----------------------------------------------------------------------------
extern "C" void kernel_launch(void* const* d_in, const int* in_sizes, int n_in,
                              void* d_out, int out_size) {
    using namespace vq16;
    const float* z   = (const float*)d_in[0];
    const float* emb = (const float*)d_in[1];
    float* out = (float*)d_out;
    const int N = in_sizes[0] / DIM;    // 32768

    cudaFuncSetAttribute(tc_pass, cudaFuncAttributeMaxDynamicSharedMemorySize, SM_TOT);

    norms_fused<<<(KCNT + N) / 8, 256>>>(emb, z);
    prep<<<KCNT * DIM / 4 / 256, 256>>>(emb);
    tc_pass<<<N / BM, 256, SM_TOT>>>(z);
    rescore<<<N * 32 / 256, 256>>>(z, emb);
    finalize<<<N / 2, 256>>>(z, emb, out, N);
    reduce_loss<<<1, 512>>>(out, N);
}